// round 6
// baseline (speedup 1.0000x reference)
#include <cuda_runtime.h>
#include <cstdint>

// Problem constants
#define Bc 64
#define Cc 256
#define Hc 28
#define Wc 28
#define Nc 784          // H*W
#define CH 16           // channel chunk (double-buffered)
#define NCHUNK (Cc / CH)
#define BROWS 4         // max grid2 band rows (provable <= 4)
#define BN (BROWS * Wc) // 112
#define MAXP 512        // max pairs per block (provable <= ~400)

__device__ double g_sum[2];
__device__ unsigned long long g_cnt[2];

__global__ void cl_init_kernel() {
    g_sum[0] = 0.0; g_sum[1] = 0.0;
    g_cnt[0] = 0ull; g_cnt[1] = 0ull;
}

__device__ __forceinline__ void cp_async16(unsigned int smem_addr, const void* gptr) {
    asm volatile("cp.async.cg.shared.global [%0], [%1], 16;\n" :: "r"(smem_addr), "l"(gptr));
}
__device__ __forceinline__ void cp_async_commit() {
    asm volatile("cp.async.commit_group;\n" ::: "memory");
}
__device__ __forceinline__ void cp_async_wait1() {
    asm volatile("cp.async.wait_group 1;\n" ::: "memory");
}
__device__ __forceinline__ void cp_async_wait0() {
    asm volatile("cp.async.wait_group 0;\n" ::: "memory");
}

// per-buffer tile sizes (words)
#define YBUF (2 * CH * Wc)       // 896
#define ZBUF (2 * CH * BN + 4)   // 3588 (view1 at +CH*BN+4 for bank decorrelation)
#define ZOFF1 (CH * BN + 4)

__global__ __launch_bounds__(256) void cl_main_kernel(
    const float* __restrict__ y1, const float* __restrict__ y2,
    const float* __restrict__ z1, const float* __restrict__ z2,
    const float* __restrict__ g1, const float* __restrict__ g2)
{
    __shared__ float ysm[2][YBUF];
    __shared__ float zsm[2][ZBUF];
    __shared__ float yn2[2][Wc];
    __shared__ float zn2[2][BN];
    __shared__ float s_g1x[Wc];
    __shared__ float s_g2y[BN];
    __shared__ float s_g2x[BN];
    __shared__ int   s_pairs[MAXP];     // (view<<16)|(nl<<8)|j
    __shared__ int   s_np;
    __shared__ int   s_r0, s_nb;
    __shared__ float s_bin1, s_bin2, s_g1y;
    __shared__ double warp_s0[8], warp_s1[8];
    __shared__ int    warp_c0[8], warp_c1[8];

    const int yr = blockIdx.x;  // grid1 row 0..27
    const int b  = blockIdx.y;  // batch
    const int t  = threadIdx.x;

    const float* g1b = g1 + (size_t)b * 2 * Nc;
    const float* g2b = g2 + (size_t)b * 2 * Nc;

    if (t == 0) {
        float d1y = g1b[29] - g1b[0];
        float d1x = g1b[Nc + 29] - g1b[Nc + 0];
        float bin1 = __fsqrt_rn(__fadd_rn(__fmul_rn(d1y, d1y), __fmul_rn(d1x, d1x)));
        float d2y = g2b[29] - g2b[0];
        float d2x = g2b[Nc + 29] - g2b[Nc + 0];
        float bin2 = __fsqrt_rn(__fadd_rn(__fmul_rn(d2y, d2y), __fmul_rn(d2x, d2x)));
        s_bin1 = bin1; s_bin2 = bin2;
        float g1y = g1b[yr * Wc];
        s_g1y = g1y;
        float thrm = 0.7f * fmaxf(bin1, bin2) * 1.0002f + 1e-3f;
        int r0 = -1, r1 = -2;
        for (int my = 0; my < Hc; my++) {
            float gy = g2b[my * Wc];
            if (fabsf(gy - g1y) <= thrm) { if (r0 < 0) r0 = my; r1 = my; }
        }
        int nb = r1 - r0 + 1;
        if (nb < 0) nb = 0;
        if (nb > BROWS) nb = BROWS;
        s_r0 = r0; s_nb = nb;
        s_np = 0;
    }
    __syncthreads();

    const int nb = s_nb;
    if (nb == 0) return;                // uniform exit, nothing issued yet
    const int r0 = s_r0;
    const int m0 = r0 * Wc;
    const int bandn = nb * Wc;          // <= 112, multiple of 28
    const int nqz = bandn >> 2;         // 16B groups per z row (<=28)
    const int nbase = yr * Wc;

    // view 0: y1 vs z2 ; view 1: y2 vs z1
    const float* ya[2] = { y1 + (size_t)b * Cc * Nc, y2 + (size_t)b * Cc * Nc };
    const float* za[2] = { z2 + (size_t)b * Cc * Nc, z1 + (size_t)b * Cc * Nc };

    unsigned int ysm0 = (unsigned int)__cvta_generic_to_shared(&ysm[0][0]);
    unsigned int zsm0 = (unsigned int)__cvta_generic_to_shared(&zsm[0][0]);

    // ---- issue chunk-0 loads immediately (overlap DRAM latency with mask eval) ----
    {
        const int cc = 0;
        unsigned int yb = ysm0;              // buffer 0
        unsigned int zb = zsm0;
        for (int e = t; e < 2 * CH * (Wc / 4); e += 256) {
            int v  = e / (CH * (Wc / 4));
            int r  = e - v * (CH * (Wc / 4));
            int cl = r / (Wc / 4);
            int q  = r - cl * (Wc / 4);
            unsigned int saddr = yb + (unsigned int)(((v * CH + cl) * Wc + (q << 2)) * 4);
            cp_async16(saddr, ya[v] + (size_t)(cc + cl) * Nc + nbase + (q << 2));
        }
        for (int e = t; e < 2 * CH * nqz; e += 256) {
            int v  = e / (CH * nqz);
            int r  = e - v * (CH * nqz);
            int cl = r / nqz;
            int q  = r - cl * nqz;
            unsigned int saddr = zb + (unsigned int)((v * ZOFF1 + cl * BN + (q << 2)) * 4);
            cp_async16(saddr, za[v] + (size_t)(cc + cl) * Nc + m0 + (q << 2));
        }
        cp_async_commit();
    }

    // stage grid coordinates + zero norms
    if (t < Wc) s_g1x[t] = g1b[Nc + yr * Wc + t];
    for (int j = t; j < bandn; j += 256) {
        s_g2y[j] = g2b[m0 + j];
        s_g2x[j] = g2b[Nc + m0 + j];
    }
    if (t < 2 * Wc) yn2[t / Wc][t % Wc] = 0.f;
    for (int j = t; j < 2 * BN; j += 256) zn2[j / BN][j % BN] = 0.f;
    __syncthreads();

    // ---- exact mask evaluation (bit-matches reference float ops) ----
    const float bin1 = s_bin1, bin2 = s_bin2, g1y = s_g1y;
    for (int idx = t; idx < Wc * bandn; idx += 256) {
        int nl = idx / bandn;
        int j  = idx - nl * bandn;
        float dy = g1y - s_g2y[j];
        float dx = s_g1x[nl] - s_g2x[j];
        float dist = __fsqrt_rn(__fadd_rn(__fmul_rn(dy, dy), __fmul_rn(dx, dx)));
        bool m1 = (__fdiv_rn(dist, bin1) <= 0.7f);
        bool m2 = (__fdiv_rn(dist, bin2) <= 0.7f);
        if (m1) { int p = atomicAdd(&s_np, 1); if (p < MAXP) s_pairs[p] = (0 << 16) | (nl << 8) | j; }
        if (m2) { int p = atomicAdd(&s_np, 1); if (p < MAXP) s_pairs[p] = (1 << 16) | (nl << 8) | j; }
    }
    __syncthreads();
    int np = s_np; if (np > MAXP) np = MAXP;
    if (np == 0) { cp_async_wait0(); __syncthreads(); return; }   // drain before exit

    float dacc[2] = {0.f, 0.f};

    // ---- 2-stage pipelined chunk loop ----
    for (int ci = 0; ci < NCHUNK; ci++) {
        const int cur = ci & 1;
        // prefetch next chunk into the other buffer (that buffer's readers
        // finished at the end-of-iteration barrier of ci-1)
        if (ci + 1 < NCHUNK) {
            const int cc = (ci + 1) * CH;
            const int nxt = cur ^ 1;
            unsigned int yb = ysm0 + (unsigned int)(nxt * YBUF * 4);
            unsigned int zb = zsm0 + (unsigned int)(nxt * ZBUF * 4);
            for (int e = t; e < 2 * CH * (Wc / 4); e += 256) {
                int v  = e / (CH * (Wc / 4));
                int r  = e - v * (CH * (Wc / 4));
                int cl = r / (Wc / 4);
                int q  = r - cl * (Wc / 4);
                unsigned int saddr = yb + (unsigned int)(((v * CH + cl) * Wc + (q << 2)) * 4);
                cp_async16(saddr, ya[v] + (size_t)(cc + cl) * Nc + nbase + (q << 2));
            }
            for (int e = t; e < 2 * CH * nqz; e += 256) {
                int v  = e / (CH * nqz);
                int r  = e - v * (CH * nqz);
                int cl = r / nqz;
                int q  = r - cl * nqz;
                unsigned int saddr = zb + (unsigned int)((v * ZOFF1 + cl * BN + (q << 2)) * 4);
                cp_async16(saddr, za[v] + (size_t)(cc + cl) * Nc + m0 + (q << 2));
            }
        }
        cp_async_commit();           // commit prefetch group (possibly empty)
        cp_async_wait1();            // current chunk's group complete
        __syncthreads();

        const float* yv0 = &ysm[cur][0];
        const float* zv0 = &zsm[cur][0];

        // column norms^2 (lanes take consecutive cols -> conflict-free)
        for (int col = t; col < 2 * Wc; col += 256) {
            int v = col / Wc, nl = col - v * Wc;
            const float* yv = yv0 + v * CH * Wc;
            float s = 0.f;
            #pragma unroll
            for (int cl = 0; cl < CH; cl++) { float x = yv[cl * Wc + nl]; s += x * x; }
            yn2[v][nl] += s;
        }
        for (int col = t; col < 2 * bandn; col += 256) {
            int v = col / bandn, j = col - v * bandn;
            const float* zv = zv0 + v * ZOFF1;
            float s = 0.f;
            #pragma unroll
            for (int cl = 0; cl < CH; cl++) { float x = zv[cl * BN + j]; s += x * x; }
            zn2[v][j] += s;
        }
        // pair dots
        for (int p = t, k = 0; p < np; p += 256, k++) {
            int pr = s_pairs[p];
            int v = pr >> 16, nl = (pr >> 8) & 255, j = pr & 255;
            const float* yv = yv0 + v * CH * Wc;
            const float* zv = zv0 + v * ZOFF1;
            float s = 0.f;
            #pragma unroll
            for (int cl = 0; cl < CH; cl++) s += yv[cl * Wc + nl] * zv[cl * BN + j];
            dacc[k] += s;
        }
        __syncthreads();             // readers done before this buffer is refilled
    }

    // per-pair cosine sim, double accumulation
    double ls0 = 0.0, ls1 = 0.0;
    int lc0 = 0, lc1 = 0;
    for (int p = t, k = 0; p < np; p += 256, k++) {
        int pr = s_pairs[p];
        int v = pr >> 16, nl = (pr >> 8) & 255, j = pr & 255;
        float den = fmaxf(__fsqrt_rn(yn2[v][nl] * zn2[v][j]), 1e-8f);
        float sim = dacc[k] / den;
        if (v == 0) { ls0 += (double)sim; lc0++; }
        else        { ls1 += (double)sim; lc1++; }
    }

    for (int off = 16; off; off >>= 1) {
        ls0 += __shfl_down_sync(0xffffffffu, ls0, off);
        ls1 += __shfl_down_sync(0xffffffffu, ls1, off);
        lc0 += __shfl_down_sync(0xffffffffu, lc0, off);
        lc1 += __shfl_down_sync(0xffffffffu, lc1, off);
    }
    int wid = t >> 5, lane = t & 31;
    if (lane == 0) { warp_s0[wid] = ls0; warp_s1[wid] = ls1; warp_c0[wid] = lc0; warp_c1[wid] = lc1; }
    __syncthreads();
    if (t == 0) {
        double S0 = 0.0, S1 = 0.0; int C0 = 0, C1 = 0;
        #pragma unroll
        for (int w = 0; w < 8; w++) { S0 += warp_s0[w]; S1 += warp_s1[w]; C0 += warp_c0[w]; C1 += warp_c1[w]; }
        atomicAdd(&g_sum[0], S0);
        atomicAdd(&g_sum[1], S1);
        atomicAdd(&g_cnt[0], (unsigned long long)C0);
        atomicAdd(&g_cnt[1], (unsigned long long)C1);
    }
}

__global__ void cl_fin_kernel(float* __restrict__ out) {
    double l0 = g_cnt[0] ? g_sum[0] / (double)g_cnt[0] : 0.0;
    double l1 = g_cnt[1] ? g_sum[1] / (double)g_cnt[1] : 0.0;
    out[0] = (float)(-(l0 + l1));
}

extern "C" void kernel_launch(void* const* d_in, const int* in_sizes, int n_in,
                              void* d_out, int out_size) {
    (void)in_sizes; (void)n_in; (void)out_size;
    const float* y1 = (const float*)d_in[0];
    const float* y2 = (const float*)d_in[1];
    const float* z1 = (const float*)d_in[2];
    const float* z2 = (const float*)d_in[3];
    const float* g1 = (const float*)d_in[4];
    const float* g2 = (const float*)d_in[5];

    cl_init_kernel<<<1, 1>>>();
    dim3 grid(Hc, Bc);
    cl_main_kernel<<<grid, 256>>>(y1, y2, z1, z2, g1, g2);
    cl_fin_kernel<<<1, 1>>>((float*)d_out);
}

// round 7
// speedup vs baseline: 1.0088x; 1.0088x over previous
#include <cuda_runtime.h>
#include <cstdint>

// Problem constants
#define Bc 64
#define Cc 256
#define Hc 28
#define Wc 28
#define Nc 784          // H*W
#define CH 32           // channel chunk
#define NCHUNK (Cc / CH)
#define BROWS 4         // max grid2 band rows (provable <= 4)
#define BN (BROWS * Wc) // 112
#define MAXK 16         // max pairs per (view,column); provable <= ~9
#define NG (2 * Wc)     // 56 groups: view*28 + column
#define ZOFF1 (CH * BN + 4)

__device__ double g_sum[2];
__device__ unsigned long long g_cnt[2];

__global__ void cl_init_kernel() {
    g_sum[0] = 0.0; g_sum[1] = 0.0;
    g_cnt[0] = 0ull; g_cnt[1] = 0ull;
}

__device__ __forceinline__ void cp_async16(unsigned int smem_addr, const void* gptr) {
    asm volatile("cp.async.cg.shared.global [%0], [%1], 16;\n" :: "r"(smem_addr), "l"(gptr));
}
__device__ __forceinline__ void cp_async_commit_wait() {
    asm volatile("cp.async.commit_group;\n" ::: "memory");
    asm volatile("cp.async.wait_group 0;\n" ::: "memory");
}

__global__ __launch_bounds__(256) void cl_main_kernel(
    const float* __restrict__ y1, const float* __restrict__ y2,
    const float* __restrict__ z1, const float* __restrict__ z2,
    const float* __restrict__ g1, const float* __restrict__ g2)
{
    __shared__ float ysm[2 * CH * Wc];       // [view][c][nl]
    __shared__ float zsm[2 * CH * BN + 4];   // [view][c][j], view1 at +ZOFF1
    __shared__ float yn2[2][Wc];
    __shared__ float zn2[2][BN];
    __shared__ float s_g1x[Wc];
    __shared__ float s_g2y[BN];
    __shared__ float s_g2x[BN];
    __shared__ int   s_cnt[NG];
    __shared__ int   s_jl[NG * MAXK];
    __shared__ float s_dot[NG * MAXK];
    __shared__ int   s_r0, s_nb;
    __shared__ float s_bin1, s_bin2, s_g1y;
    __shared__ double s_acc[2];
    __shared__ unsigned int s_pc[2];

    const int yr = blockIdx.x;  // grid1 row 0..27
    const int b  = blockIdx.y;  // batch
    const int t  = threadIdx.x;

    const float* g1b = g1 + (size_t)b * 2 * Nc;
    const float* g2b = g2 + (size_t)b * 2 * Nc;

    if (t == 0) {
        float d1y = g1b[29] - g1b[0];
        float d1x = g1b[Nc + 29] - g1b[Nc + 0];
        float bin1 = __fsqrt_rn(__fadd_rn(__fmul_rn(d1y, d1y), __fmul_rn(d1x, d1x)));
        float d2y = g2b[29] - g2b[0];
        float d2x = g2b[Nc + 29] - g2b[Nc + 0];
        float bin2 = __fsqrt_rn(__fadd_rn(__fmul_rn(d2y, d2y), __fmul_rn(d2x, d2x)));
        s_bin1 = bin1; s_bin2 = bin2;
        float g1y = g1b[yr * Wc];
        s_g1y = g1y;
        float thrm = 0.7f * fmaxf(bin1, bin2) * 1.0002f + 1e-3f;
        int r0 = -1, r1 = -2;
        for (int my = 0; my < Hc; my++) {
            float gy = g2b[my * Wc];
            if (fabsf(gy - g1y) <= thrm) { if (r0 < 0) r0 = my; r1 = my; }
        }
        int nb = r1 - r0 + 1;
        if (nb < 0) nb = 0;
        if (nb > BROWS) nb = BROWS;
        s_r0 = r0; s_nb = nb;
        s_acc[0] = 0.0; s_acc[1] = 0.0;
        s_pc[0] = 0u; s_pc[1] = 0u;
    }
    __syncthreads();

    const int nb = s_nb;
    if (nb == 0) return;                // uniform exit
    const int r0 = s_r0;
    const int m0 = r0 * Wc;
    const int bandn = nb * Wc;          // <= 112, multiple of 28
    const int nqz = bandn >> 2;
    const int nbase = yr * Wc;

    // stage grid coords, zero accumulators and group tables
    if (t < Wc) s_g1x[t] = g1b[Nc + yr * Wc + t];
    for (int j = t; j < bandn; j += 256) {
        s_g2y[j] = g2b[m0 + j];
        s_g2x[j] = g2b[Nc + m0 + j];
    }
    if (t < 2 * Wc) yn2[t / Wc][t % Wc] = 0.f;
    for (int j = t; j < 2 * BN; j += 256) zn2[j / BN][j % BN] = 0.f;
    if (t < NG) s_cnt[t] = 0;
    for (int k = t; k < NG * MAXK; k += 256) s_dot[k] = 0.f;
    __syncthreads();

    // ---- exact mask evaluation (bit-matches reference float ops) ----
    const float bin1 = s_bin1, bin2 = s_bin2, g1y = s_g1y;
    for (int idx = t; idx < Wc * bandn; idx += 256) {
        int nl = idx / bandn;
        int j  = idx - nl * bandn;
        float dy = g1y - s_g2y[j];
        float dx = s_g1x[nl] - s_g2x[j];
        float dist = __fsqrt_rn(__fadd_rn(__fmul_rn(dy, dy), __fmul_rn(dx, dx)));
        bool m1 = (__fdiv_rn(dist, bin1) <= 0.7f);
        bool m2 = (__fdiv_rn(dist, bin2) <= 0.7f);
        if (m1) { int k = atomicAdd(&s_cnt[nl], 1);      if (k < MAXK) s_jl[nl * MAXK + k] = j; }
        if (m2) { int k = atomicAdd(&s_cnt[Wc + nl], 1); if (k < MAXK) s_jl[(Wc + nl) * MAXK + k] = j; }
    }
    __syncthreads();

    // view 0: y1 vs z2 ; view 1: y2 vs z1
    const float* ya[2] = { y1 + (size_t)b * Cc * Nc, y2 + (size_t)b * Cc * Nc };
    const float* za[2] = { z2 + (size_t)b * Cc * Nc, z1 + (size_t)b * Cc * Nc };

    unsigned int ysm0 = (unsigned int)__cvta_generic_to_shared(ysm);
    unsigned int zsm0 = (unsigned int)__cvta_generic_to_shared(zsm);

    // dot-phase thread mapping: warp0 -> view0 cols, warp1 -> view1 cols
    const int dv  = t >> 5;
    const int dnl = t & 31;
    const bool dotthr = (t < 64) && (dnl < Wc);
    int dg = 0, dcnt = 0;
    if (dotthr) { dg = dv * Wc + dnl; dcnt = s_cnt[dg]; if (dcnt > MAXK) dcnt = MAXK; }

    // ---- chunk loop ----
    for (int ci = 0; ci < NCHUNK; ci++) {
        const int cc = ci * CH;
        __syncthreads();   // previous chunk's readers done before refill
        // y tiles: 2*CH*7 = 448 cp.async of 16B
        for (int e = t; e < 2 * CH * (Wc / 4); e += 256) {
            int v  = e / (CH * (Wc / 4));
            int r  = e - v * (CH * (Wc / 4));
            int cl = r / (Wc / 4);
            int q  = r - cl * (Wc / 4);
            unsigned int saddr = ysm0 + (unsigned int)(((v * CH + cl) * Wc + (q << 2)) * 4);
            cp_async16(saddr, ya[v] + (size_t)(cc + cl) * Nc + nbase + (q << 2));
        }
        // z tiles
        for (int e = t; e < 2 * CH * nqz; e += 256) {
            int v  = e / (CH * nqz);
            int r  = e - v * (CH * nqz);
            int cl = r / nqz;
            int q  = r - cl * nqz;
            unsigned int saddr = zsm0 + (unsigned int)((v * ZOFF1 + cl * BN + (q << 2)) * 4);
            cp_async16(saddr, za[v] + (size_t)(cc + cl) * Nc + m0 + (q << 2));
        }
        cp_async_commit_wait();
        __syncthreads();

        // column norms^2 (lanes: consecutive cols -> conflict-free)
        for (int col = t; col < 2 * Wc; col += 256) {
            int v = col / Wc, nl = col - v * Wc;
            const float* yv = ysm + v * CH * Wc;
            float s = 0.f;
            #pragma unroll
            for (int cl = 0; cl < CH; cl++) { float x = yv[cl * Wc + nl]; s += x * x; }
            yn2[v][nl] += s;
        }
        for (int col = t; col < 2 * bandn; col += 256) {
            int v = col / bandn, j = col - v * bandn;
            const float* zv = zsm + v * ZOFF1;
            float s = 0.f;
            #pragma unroll
            for (int cl = 0; cl < CH; cl++) { float x = zv[cl * BN + j]; s += x * x; }
            zn2[v][j] += s;
        }

        // column-owned pair dots: y column cached in registers, reused for all pairs
        if (dotthr && dcnt > 0) {
            const float* yv = ysm + dv * CH * Wc;
            const float* zv = zsm + dv * ZOFF1;
            float yreg[CH];
            #pragma unroll
            for (int cl = 0; cl < CH; cl++) yreg[cl] = yv[cl * Wc + dnl];
            #pragma unroll 1
            for (int k = 0; k < dcnt; k++) {
                int j = s_jl[dg * MAXK + k];
                float s = 0.f;
                #pragma unroll
                for (int cl = 0; cl < CH; cl++) s += yreg[cl] * zv[cl * BN + j];
                s_dot[dg * MAXK + k] += s;
            }
        }
    }
    __syncthreads();

    // ---- per-pair cosine sims, double accumulation ----
    if (dotthr && dcnt > 0) {
        double ls = 0.0;
        for (int k = 0; k < dcnt; k++) {
            int j = s_jl[dg * MAXK + k];
            float den = fmaxf(__fsqrt_rn(yn2[dv][dnl] * zn2[dv][j]), 1e-8f);
            ls += (double)(s_dot[dg * MAXK + k] / den);
        }
        atomicAdd(&s_acc[dv], ls);
        atomicAdd(&s_pc[dv], (unsigned int)dcnt);
    }
    __syncthreads();
    if (t == 0) {
        atomicAdd(&g_sum[0], s_acc[0]);
        atomicAdd(&g_sum[1], s_acc[1]);
        atomicAdd(&g_cnt[0], (unsigned long long)s_pc[0]);
        atomicAdd(&g_cnt[1], (unsigned long long)s_pc[1]);
    }
}

__global__ void cl_fin_kernel(float* __restrict__ out) {
    double l0 = g_cnt[0] ? g_sum[0] / (double)g_cnt[0] : 0.0;
    double l1 = g_cnt[1] ? g_sum[1] / (double)g_cnt[1] : 0.0;
    out[0] = (float)(-(l0 + l1));
}

extern "C" void kernel_launch(void* const* d_in, const int* in_sizes, int n_in,
                              void* d_out, int out_size) {
    (void)in_sizes; (void)n_in; (void)out_size;
    const float* y1 = (const float*)d_in[0];
    const float* y2 = (const float*)d_in[1];
    const float* z1 = (const float*)d_in[2];
    const float* z2 = (const float*)d_in[3];
    const float* g1 = (const float*)d_in[4];
    const float* g2 = (const float*)d_in[5];

    cl_init_kernel<<<1, 1>>>();
    dim3 grid(Hc, Bc);
    cl_main_kernel<<<grid, 256>>>(y1, y2, z1, z2, g1, g2);
    cl_fin_kernel<<<1, 1>>>((float*)d_out);
}